// round 2
// baseline (speedup 1.0000x reference)
#include <cuda_runtime.h>
#include <cuda_bf16.h>
#include <stdint.h>

// MinibatchDiscrimination fused kernel for GB300 (sm_103a)
// out[n, 0:256]  = x[n, :]                       (exact fp32 passthrough)
// out[n, 256+k1] = sum_d exp(-sum_k2 |M[n,k2,d]-M[n,k1,d]|),  M = x @ T
//
// R2: 512 threads/CTA, acc tile halved -> ~60 regs -> 32 warps/SM (2x occ).
//     Phase-3 broadcasts via LDS.128.

#define BM        32
#define NROWS     16384
#define FEAT      256
#define NCOLS     512      // NUM_KERNELS * KERNEL_DIM = 32*16
#define OUTC      288
#define XS_STRIDE 132      // uint32 (bf16x2) words per xs row: 128 data + 4 pad
#define MS_STRIDE 516      // floats per Ms row: 512 data + 4 pad
#define SMEM_BYTES (BM*XS_STRIDE*4 + BM*MS_STRIDE*4)   // 16896 + 66048 = 82944
#define THREADS   512

// Packed T fragments: [kiter(16)][ntpair(32)][lane(32)] -> uint4
//   .x/.y = B-frag regs (b0,b1) for n-tile 2*ntpair, .z/.w = for n-tile 2*ntpair+1
__device__ uint4 g_Tperm[16 * 32 * 32];

__global__ void convert_T_kernel(const float* __restrict__ T) {
    int tid  = blockIdx.x * blockDim.x + threadIdx.x;   // one thread per uint32 (65536 total)
    int j    = tid & 3;           // which u32 within the uint4
    int lane = (tid >> 2) & 31;
    int ntp  = (tid >> 7) & 31;   // n-tile pair index (global)
    int kit  = tid >> 12;         // k iteration (k0 = kit*16)
    int nt   = ntp * 2 + (j >> 1);   // global 8-col n-tile
    int rg   = j & 1;                // 0 -> b0 (k0+2tg), 1 -> b1 (k0+8+2tg)
    int gid  = lane >> 2, tg = lane & 3;
    int n    = nt * 8 + gid;
    int k    = kit * 16 + rg * 8 + tg * 2;
    __nv_bfloat162 v = __floats2bfloat162_rn(T[k * NCOLS + n], T[(k + 1) * NCOLS + n]);
    ((uint32_t*)g_Tperm)[tid] = *reinterpret_cast<uint32_t*>(&v);
}

__device__ __forceinline__ unsigned long long f2add(unsigned long long a, unsigned long long b) {
    unsigned long long r;
    asm("add.rn.f32x2 %0, %1, %2;" : "=l"(r) : "l"(a), "l"(b));
    return r;
}

#define MMA_BF16(c, a0, a1, a2, a3, b0, b1)                                   \
    asm volatile(                                                             \
        "mma.sync.aligned.m16n8k16.row.col.f32.bf16.bf16.f32 "                \
        "{%0,%1,%2,%3}, {%4,%5,%6,%7}, {%8,%9}, {%0,%1,%2,%3};"               \
        : "+f"(c[0]), "+f"(c[1]), "+f"(c[2]), "+f"(c[3])                      \
        : "r"(a0), "r"(a1), "r"(a2), "r"(a3), "r"(b0), "r"(b1))

__global__ __launch_bounds__(THREADS, 2) void fused_kernel(const float* __restrict__ x,
                                                           float* __restrict__ out) {
    extern __shared__ char smem[];
    uint32_t* xs32 = (uint32_t*)smem;                     // [BM][XS_STRIDE] bf16x2 words
    float*    Ms   = (float*)(smem + BM * XS_STRIDE * 4); // [BM][MS_STRIDE]

    int rowbase = blockIdx.x * BM;
    int tid = threadIdx.x;

    // ---- Phase 1: load x tile, fp32 passthrough to out, bf16 into smem ----
    {
        const float4* xin = (const float4*)(x + (size_t)rowbase * FEAT);
        #pragma unroll
        for (int i = 0; i < 4; i++) {
            int f  = tid + i * THREADS;   // 0..2047 float4s (32 rows x 64)
            int r  = f >> 6, c4 = f & 63;
            float4 g = xin[r * 64 + c4];
            ((float4*)(out + (size_t)(rowbase + r) * OUTC))[c4] = g;
            __nv_bfloat162 p0 = __floats2bfloat162_rn(g.x, g.y);
            __nv_bfloat162 p1 = __floats2bfloat162_rn(g.z, g.w);
            xs32[r * XS_STRIDE + c4 * 2]     = *reinterpret_cast<uint32_t*>(&p0);
            xs32[r * XS_STRIDE + c4 * 2 + 1] = *reinterpret_cast<uint32_t*>(&p1);
        }
    }
    __syncthreads();

    int w = tid >> 5, lane = tid & 31;
    int gid = lane >> 2, tg = lane & 3;

    // ---- Phase 2: M[32][512] = x_tile @ T via mma.sync bf16 (16 warps) ----
    {
        int r0 = (w & 1) * 16;     // warp row tile (2-way split)
        int cw = (w >> 1);         // warp col tile 0..7 (64 cols each)
        float acc[8][4];
        #pragma unroll
        for (int i = 0; i < 8; i++) { acc[i][0] = acc[i][1] = acc[i][2] = acc[i][3] = 0.f; }

        #pragma unroll
        for (int kit = 0; kit < 16; kit++) {
            uint32_t a0 = xs32[(r0 + gid)     * XS_STRIDE + kit * 8 + tg];
            uint32_t a1 = xs32[(r0 + gid + 8) * XS_STRIDE + kit * 8 + tg];
            uint32_t a2 = xs32[(r0 + gid)     * XS_STRIDE + kit * 8 + 4 + tg];
            uint32_t a3 = xs32[(r0 + gid + 8) * XS_STRIDE + kit * 8 + 4 + tg];
            const uint4* tp = &g_Tperm[(kit * 32 + cw * 4) * 32 + lane];
            #pragma unroll
            for (int q = 0; q < 4; q++) {
                uint4 b = tp[q * 32];
                MMA_BF16(acc[2 * q],     a0, a1, a2, a3, b.x, b.y);
                MMA_BF16(acc[2 * q + 1], a0, a1, a2, a3, b.z, b.w);
            }
        }
        #pragma unroll
        for (int p = 0; p < 8; p++) {
            int col = cw * 64 + p * 8 + tg * 2;
            *(float2*)&Ms[(r0 + gid)     * MS_STRIDE + col] = make_float2(acc[p][0], acc[p][1]);
            *(float2*)&Ms[(r0 + gid + 8) * MS_STRIDE + col] = make_float2(acc[p][2], acc[p][3]);
        }
    }
    __syncthreads();

    // ---- Phase 3: pairwise L1 + exp. One warp per 2 rows, lane = k1. ----
    const unsigned long long SGN  = 0x8000000080000000ULL;
    const unsigned long long ABSM = 0x7FFFFFFF7FFFFFFFULL;
    #pragma unroll
    for (int rr = 0; rr < 2; rr++) {
        int n = w * 2 + rr;
        unsigned long long nv[8], ac[8];
        {
            const ulonglong2* vr = (const ulonglong2*)&Ms[n * MS_STRIDE + lane * 16];
            #pragma unroll
            for (int j = 0; j < 4; j++) {
                ulonglong2 v = vr[j];
                nv[2 * j]     = v.x ^ SGN;
                nv[2 * j + 1] = v.y ^ SGN;
                ac[2 * j] = ac[2 * j + 1] = 0ULL;
            }
        }

        const ulonglong2* mr = (const ulonglong2*)&Ms[n * MS_STRIDE];
        #pragma unroll 4
        for (int k2 = 0; k2 < 32; k2++) {
            #pragma unroll
            for (int j = 0; j < 4; j++) {
                ulonglong2 m = mr[k2 * 4 + j];                 // 16B broadcast
                unsigned long long t0 = f2add(m.x, nv[2 * j]);     // packed diffs
                unsigned long long t1 = f2add(m.y, nv[2 * j + 1]);
                ac[2 * j]     = f2add(ac[2 * j],     t0 & ABSM);   // packed += |diff|
                ac[2 * j + 1] = f2add(ac[2 * j + 1], t1 & ABSM);
            }
        }
        float s = 0.f;
        #pragma unroll
        for (int j2 = 0; j2 < 8; j2++) {
            s += __expf(-__uint_as_float((unsigned)(ac[j2] & 0xFFFFFFFFu)));
            s += __expf(-__uint_as_float((unsigned)(ac[j2] >> 32)));
        }
        out[(size_t)(rowbase + n) * OUTC + FEAT + lane] = s;
    }
}

extern "C" void kernel_launch(void* const* d_in, const int* in_sizes, int n_in,
                              void* d_out, int out_size) {
    const float* x = (const float*)d_in[0];
    const float* T = (const float*)d_in[1];
    float* out = (float*)d_out;

    convert_T_kernel<<<256, 256>>>(T);

    cudaFuncSetAttribute(fused_kernel, cudaFuncAttributeMaxDynamicSharedMemorySize, SMEM_BYTES);
    fused_kernel<<<NROWS / BM, THREADS, SMEM_BYTES>>>(x, out);
}

// round 4
// speedup vs baseline: 1.0444x; 1.0444x over previous
#include <cuda_runtime.h>
#include <cuda_bf16.h>
#include <stdint.h>

// MinibatchDiscrimination fused kernel for GB300 (sm_103a)
// out[n, 0:256]  = x[n, :]                       (exact fp32 passthrough)
// out[n, 256+k1] = sum_d exp(-sum_k2 |M[n,k2,d]-M[n,k1,d]|),  M = x @ T
//
// R3: BM=64, each warp covers all 64 rows x 32 cols -> each T fragment loaded
//     exactly once per CTA (B traffic 256MB -> 64MB). A frags via ldmatrix.x4.

#define BM        64
#define NROWS     16384
#define FEAT      256
#define NCOLS     512      // NUM_KERNELS * KERNEL_DIM = 32*16
#define OUTC      288
#define XS_STRIDE 132      // uint32 (bf16x2) words per xs row: 128 data + 4 pad
#define MS_STRIDE 516      // floats per Ms row: 512 data + 4 pad
#define SMEM_BYTES (BM*XS_STRIDE*4 + BM*MS_STRIDE*4)   // 33792 + 132096 = 165888
#define THREADS   512

// Packed T fragments: [kiter(16)][ntpair(32)][lane(32)] -> uint4
//   .x/.y = B-frag regs (b0,b1) for n-tile 2*ntpair, .z/.w = for n-tile 2*ntpair+1
__device__ uint4 g_Tperm[16 * 32 * 32];

__global__ void convert_T_kernel(const float* __restrict__ T) {
    int tid  = blockIdx.x * blockDim.x + threadIdx.x;   // one thread per uint32 (65536 total)
    int j    = tid & 3;           // which u32 within the uint4
    int lane = (tid >> 2) & 31;
    int ntp  = (tid >> 7) & 31;   // n-tile pair index (global)
    int kit  = tid >> 12;         // k iteration (k0 = kit*16)
    int nt   = ntp * 2 + (j >> 1);   // global 8-col n-tile
    int rg   = j & 1;                // 0 -> b0 (k0+2tg), 1 -> b1 (k0+8+2tg)
    int gid  = lane >> 2, tg = lane & 3;
    int n    = nt * 8 + gid;
    int k    = kit * 16 + rg * 8 + tg * 2;
    __nv_bfloat162 v = __floats2bfloat162_rn(T[k * NCOLS + n], T[(k + 1) * NCOLS + n]);
    ((uint32_t*)g_Tperm)[tid] = *reinterpret_cast<uint32_t*>(&v);
}

__device__ __forceinline__ unsigned long long f2add(unsigned long long a, unsigned long long b) {
    unsigned long long r;
    asm("add.rn.f32x2 %0, %1, %2;" : "=l"(r) : "l"(a), "l"(b));
    return r;
}

#define MMA_BF16(c, a0, a1, a2, a3, b0, b1)                                   \
    asm volatile(                                                             \
        "mma.sync.aligned.m16n8k16.row.col.f32.bf16.bf16.f32 "                \
        "{%0,%1,%2,%3}, {%4,%5,%6,%7}, {%8,%9}, {%0,%1,%2,%3};"               \
        : "+f"(c[0]), "+f"(c[1]), "+f"(c[2]), "+f"(c[3])                      \
        : "r"(a0), "r"(a1), "r"(a2), "r"(a3), "r"(b0), "r"(b1))

__global__ __launch_bounds__(THREADS, 1) void fused_kernel(const float* __restrict__ x,
                                                           float* __restrict__ out) {
    extern __shared__ char smem[];
    uint32_t* xs32 = (uint32_t*)smem;                     // [BM][XS_STRIDE] bf16x2 words
    float*    Ms   = (float*)(smem + BM * XS_STRIDE * 4); // [BM][MS_STRIDE]

    int rowbase = blockIdx.x * BM;
    int tid = threadIdx.x;

    // ---- Phase 1: load x tile, fp32 passthrough to out, bf16 into smem ----
    {
        const float4* xin = (const float4*)(x + (size_t)rowbase * FEAT);
        #pragma unroll
        for (int i = 0; i < 8; i++) {
            int f  = tid + i * THREADS;   // 0..4095 float4s (64 rows x 64)
            int r  = f >> 6, c4 = f & 63;
            float4 g = xin[r * 64 + c4];
            ((float4*)(out + (size_t)(rowbase + r) * OUTC))[c4] = g;
            __nv_bfloat162 p0 = __floats2bfloat162_rn(g.x, g.y);
            __nv_bfloat162 p1 = __floats2bfloat162_rn(g.z, g.w);
            xs32[r * XS_STRIDE + c4 * 2]     = *reinterpret_cast<uint32_t*>(&p0);
            xs32[r * XS_STRIDE + c4 * 2 + 1] = *reinterpret_cast<uint32_t*>(&p1);
        }
    }
    __syncthreads();

    int w = tid >> 5, lane = tid & 31;
    int gid = lane >> 2, tg = lane & 3;

    // ---- Phase 2: M[64][512] = x_tile @ T via mma.sync bf16 ----
    // Warp w covers ALL 64 rows x cols [32w, 32w+32): 4 m-tiles x 4 n-tiles.
    {
        float acc[4][4][4];
        #pragma unroll
        for (int mt = 0; mt < 4; mt++)
            #pragma unroll
            for (int nt = 0; nt < 4; nt++)
                acc[mt][nt][0] = acc[mt][nt][1] = acc[mt][nt][2] = acc[mt][nt][3] = 0.f;

        // ldmatrix.x4 per-lane base: matrix m = lane>>3 covers (rows + (m&1)*8, kcols + (m>>1)*8)
        int m8 = lane >> 3, r8 = lane & 7;
        uint32_t lm_base = (uint32_t)__cvta_generic_to_shared(xs32) +
                           (((m8 & 1) * 8 + r8) * XS_STRIDE + (m8 >> 1) * 4) * 4;

        #pragma unroll 4
        for (int kit = 0; kit < 16; kit++) {
            const uint4* tp = &g_Tperm[(kit * 32 + w * 2) * 32 + lane];
            uint4 bA = tp[0];    // n-tiles 4w+0, 4w+1
            uint4 bB = tp[32];   // n-tiles 4w+2, 4w+3
            #pragma unroll
            for (int mt = 0; mt < 4; mt++) {
                uint32_t a0, a1, a2, a3;
                uint32_t addr = lm_base + (mt * 16 * XS_STRIDE + kit * 8) * 4;
                asm volatile("ldmatrix.sync.aligned.m8n8.x4.shared.b16 {%0,%1,%2,%3}, [%4];"
                             : "=r"(a0), "=r"(a1), "=r"(a2), "=r"(a3) : "r"(addr));
                MMA_BF16(acc[mt][0], a0, a1, a2, a3, bA.x, bA.y);
                MMA_BF16(acc[mt][1], a0, a1, a2, a3, bA.z, bA.w);
                MMA_BF16(acc[mt][2], a0, a1, a2, a3, bB.x, bB.y);
                MMA_BF16(acc[mt][3], a0, a1, a2, a3, bB.z, bB.w);
            }
        }
        #pragma unroll
        for (int mt = 0; mt < 4; mt++)
            #pragma unroll
            for (int nt = 0; nt < 4; nt++) {
                int col = w * 32 + nt * 8 + tg * 2;
                *(float2*)&Ms[(mt * 16 + gid)     * MS_STRIDE + col] =
                    make_float2(acc[mt][nt][0], acc[mt][nt][1]);
                *(float2*)&Ms[(mt * 16 + gid + 8) * MS_STRIDE + col] =
                    make_float2(acc[mt][nt][2], acc[mt][nt][3]);
            }
    }
    __syncthreads();

    // ---- Phase 3: pairwise L1 + exp. One warp per 4 rows, lane = k1. ----
    const unsigned long long SGN  = 0x8000000080000000ULL;
    const unsigned long long ABSM = 0x7FFFFFFF7FFFFFFFULL;
    #pragma unroll
    for (int rr = 0; rr < 4; rr++) {
        int n = w * 4 + rr;
        unsigned long long nv[8], ac[8];
        {
            const ulonglong2* vr = (const ulonglong2*)&Ms[n * MS_STRIDE + lane * 16];
            #pragma unroll
            for (int j = 0; j < 4; j++) {
                ulonglong2 v = vr[j];
                nv[2 * j]     = v.x ^ SGN;
                nv[2 * j + 1] = v.y ^ SGN;
                ac[2 * j] = ac[2 * j + 1] = 0ULL;
            }
        }

        const ulonglong2* mr = (const ulonglong2*)&Ms[n * MS_STRIDE];
        #pragma unroll 4
        for (int k2 = 0; k2 < 32; k2++) {
            #pragma unroll
            for (int j = 0; j < 4; j++) {
                ulonglong2 m = mr[k2 * 4 + j];                     // 16B broadcast
                unsigned long long t0 = f2add(m.x, nv[2 * j]);     // packed diffs
                unsigned long long t1 = f2add(m.y, nv[2 * j + 1]);
                ac[2 * j]     = f2add(ac[2 * j],     t0 & ABSM);   // packed += |diff|
                ac[2 * j + 1] = f2add(ac[2 * j + 1], t1 & ABSM);
            }
        }
        float s = 0.f;
        #pragma unroll
        for (int j2 = 0; j2 < 8; j2++) {
            s += __expf(-__uint_as_float((unsigned)(ac[j2] & 0xFFFFFFFFu)));
            s += __expf(-__uint_as_float((unsigned)(ac[j2] >> 32)));
        }
        out[(size_t)(rowbase + n) * OUTC + FEAT + lane] = s;
    }
}

extern "C" void kernel_launch(void* const* d_in, const int* in_sizes, int n_in,
                              void* d_out, int out_size) {
    const float* x = (const float*)d_in[0];
    const float* T = (const float*)d_in[1];
    float* out = (float*)d_out;

    convert_T_kernel<<<256, 256>>>(T);

    cudaFuncSetAttribute(fused_kernel, cudaFuncAttributeMaxDynamicSharedMemorySize, SMEM_BYTES);
    fused_kernel<<<NROWS / BM, THREADS, SMEM_BYTES>>>(x, out);
}

// round 5
// speedup vs baseline: 1.3119x; 1.2561x over previous
#include <cuda_runtime.h>
#include <cuda_bf16.h>
#include <stdint.h>

// MinibatchDiscrimination fused kernel for GB300 (sm_103a)
// out[n, 0:256]  = x[n, :]                       (exact fp32 passthrough)
// out[n, 256+k1] = sum_d exp(-sum_k2 |M[n,k2,d]-M[n,k1,d]|),  M = x @ T
//
// R5: phase 3 in bf16 (halves LDS writeback wavefronts + LOP3 count).
//     M stored to smem as bf16x2; pairwise L1 via add.rn.bf16x2.

#define BM        64
#define NROWS     16384
#define FEAT      256
#define NCOLS     512      // NUM_KERNELS * KERNEL_DIM = 32*16
#define OUTC      288
#define XS_STRIDE 132      // uint32 (bf16x2) words per xs row: 128 data + 4 pad
#define MSW       260      // uint32 (bf16x2) words per Ms row: 256 data + 4 pad (4gid+tg+4nt+16w distinct mod 32)
#define SMEM_BYTES (BM*XS_STRIDE*4 + BM*MSW*4)   // 33792 + 66560 = 100352
#define THREADS   512

// Packed T fragments: [kiter(16)][ntpair(32)][lane(32)] -> uint4
__device__ uint4 g_Tperm[16 * 32 * 32];

__global__ void convert_T_kernel(const float* __restrict__ T) {
    int tid  = blockIdx.x * blockDim.x + threadIdx.x;   // one thread per uint32 (65536 total)
    int j    = tid & 3;
    int lane = (tid >> 2) & 31;
    int ntp  = (tid >> 7) & 31;
    int kit  = tid >> 12;
    int nt   = ntp * 2 + (j >> 1);
    int rg   = j & 1;
    int gid  = lane >> 2, tg = lane & 3;
    int n    = nt * 8 + gid;
    int k    = kit * 16 + rg * 8 + tg * 2;
    __nv_bfloat162 v = __floats2bfloat162_rn(T[k * NCOLS + n], T[(k + 1) * NCOLS + n]);
    ((uint32_t*)g_Tperm)[tid] = *reinterpret_cast<uint32_t*>(&v);
}

__device__ __forceinline__ uint32_t bf2add(uint32_t a, uint32_t b) {
    uint32_t r;
    asm("add.rn.bf16x2 %0, %1, %2;" : "=r"(r) : "r"(a), "r"(b));
    return r;
}
__device__ __forceinline__ uint32_t cvt_bf16x2(float lo, float hi) {
    uint32_t r;
    asm("cvt.rn.bf16x2.f32 %0, %1, %2;" : "=r"(r) : "f"(hi), "f"(lo));
    return r;
}

#define MMA_BF16(c, a0, a1, a2, a3, b0, b1)                                   \
    asm volatile(                                                             \
        "mma.sync.aligned.m16n8k16.row.col.f32.bf16.bf16.f32 "                \
        "{%0,%1,%2,%3}, {%4,%5,%6,%7}, {%8,%9}, {%0,%1,%2,%3};"               \
        : "+f"(c[0]), "+f"(c[1]), "+f"(c[2]), "+f"(c[3])                      \
        : "r"(a0), "r"(a1), "r"(a2), "r"(a3), "r"(b0), "r"(b1))

__global__ __launch_bounds__(THREADS, 1) void fused_kernel(const float* __restrict__ x,
                                                           float* __restrict__ out) {
    extern __shared__ char smem[];
    uint32_t* xs32 = (uint32_t*)smem;                     // [BM][XS_STRIDE] bf16x2 words
    uint32_t* Msw  = (uint32_t*)(smem + BM * XS_STRIDE * 4); // [BM][MSW] bf16x2 words

    int rowbase = blockIdx.x * BM;
    int tid = threadIdx.x;

    // ---- Phase 1: load x tile, fp32 passthrough to out, bf16 into smem ----
    {
        const float4* xin = (const float4*)(x + (size_t)rowbase * FEAT);
        #pragma unroll
        for (int i = 0; i < 8; i++) {
            int f  = tid + i * THREADS;   // 0..4095 float4s (64 rows x 64)
            int r  = f >> 6, c4 = f & 63;
            float4 g = xin[r * 64 + c4];
            ((float4*)(out + (size_t)(rowbase + r) * OUTC))[c4] = g;
            __nv_bfloat162 p0 = __floats2bfloat162_rn(g.x, g.y);
            __nv_bfloat162 p1 = __floats2bfloat162_rn(g.z, g.w);
            xs32[r * XS_STRIDE + c4 * 2]     = *reinterpret_cast<uint32_t*>(&p0);
            xs32[r * XS_STRIDE + c4 * 2 + 1] = *reinterpret_cast<uint32_t*>(&p1);
        }
    }
    __syncthreads();

    int w = tid >> 5, lane = tid & 31;
    int gid = lane >> 2, tg = lane & 3;

    // ---- Phase 2: M[64][512] = x_tile @ T via mma.sync bf16 ----
    // Warp w covers ALL 64 rows x cols [32w, 32w+32): 4 m-tiles x 4 n-tiles.
    {
        float acc[4][4][4];
        #pragma unroll
        for (int mt = 0; mt < 4; mt++)
            #pragma unroll
            for (int nt = 0; nt < 4; nt++)
                acc[mt][nt][0] = acc[mt][nt][1] = acc[mt][nt][2] = acc[mt][nt][3] = 0.f;

        int m8 = lane >> 3, r8 = lane & 7;
        uint32_t lm_base = (uint32_t)__cvta_generic_to_shared(xs32) +
                           (((m8 & 1) * 8 + r8) * XS_STRIDE + (m8 >> 1) * 4) * 4;

        #pragma unroll 4
        for (int kit = 0; kit < 16; kit++) {
            const uint4* tp = &g_Tperm[(kit * 32 + w * 2) * 32 + lane];
            uint4 bA = tp[0];    // n-tiles 4w+0, 4w+1
            uint4 bB = tp[32];   // n-tiles 4w+2, 4w+3
            #pragma unroll
            for (int mt = 0; mt < 4; mt++) {
                uint32_t a0, a1, a2, a3;
                uint32_t addr = lm_base + (mt * 16 * XS_STRIDE + kit * 8) * 4;
                asm volatile("ldmatrix.sync.aligned.m8n8.x4.shared.b16 {%0,%1,%2,%3}, [%4];"
                             : "=r"(a0), "=r"(a1), "=r"(a2), "=r"(a3) : "r"(addr));
                MMA_BF16(acc[mt][0], a0, a1, a2, a3, bA.x, bA.y);
                MMA_BF16(acc[mt][1], a0, a1, a2, a3, bA.z, bA.w);
                MMA_BF16(acc[mt][2], a0, a1, a2, a3, bB.x, bB.y);
                MMA_BF16(acc[mt][3], a0, a1, a2, a3, bB.z, bB.w);
            }
        }
        // Store M as bf16x2 words. Word col = w*16 + nt*4 + tg  (cols w*32+nt*8+tg*2, /2)
        #pragma unroll
        for (int mt = 0; mt < 4; mt++)
            #pragma unroll
            for (int nt = 0; nt < 4; nt++) {
                int wc = w * 16 + nt * 4 + tg;
                Msw[(mt * 16 + gid)     * MSW + wc] = cvt_bf16x2(acc[mt][nt][0], acc[mt][nt][1]);
                Msw[(mt * 16 + gid + 8) * MSW + wc] = cvt_bf16x2(acc[mt][nt][2], acc[mt][nt][3]);
            }
    }
    __syncthreads();

    // ---- Phase 3: pairwise L1 + exp in bf16. One warp per 4 rows, lane = k1. ----
    const uint32_t SGN2  = 0x80008000u;
    const uint32_t ABSM2 = 0x7FFF7FFFu;
    #pragma unroll
    for (int rr = 0; rr < 4; rr++) {
        int n = w * 4 + rr;
        const uint32_t* mrow = &Msw[n * MSW];
        uint32_t nv[8], ac[8];
        {
            uint4 v0 = *(const uint4*)(mrow + lane * 8);
            uint4 v1 = *(const uint4*)(mrow + lane * 8 + 4);
            nv[0] = v0.x ^ SGN2; nv[1] = v0.y ^ SGN2; nv[2] = v0.z ^ SGN2; nv[3] = v0.w ^ SGN2;
            nv[4] = v1.x ^ SGN2; nv[5] = v1.y ^ SGN2; nv[6] = v1.z ^ SGN2; nv[7] = v1.w ^ SGN2;
            #pragma unroll
            for (int j = 0; j < 8; j++) ac[j] = 0u;
        }

        #pragma unroll 8
        for (int k2 = 0; k2 < 32; k2++) {
            uint4 m0 = *(const uint4*)(mrow + k2 * 8);       // broadcast 16B
            uint4 m1 = *(const uint4*)(mrow + k2 * 8 + 4);   // broadcast 16B
            uint32_t m[8] = {m0.x, m0.y, m0.z, m0.w, m1.x, m1.y, m1.z, m1.w};
            #pragma unroll
            for (int j = 0; j < 8; j++) {
                uint32_t t = bf2add(m[j], nv[j]);            // packed (M[k2,d]-M[k1,d])
                ac[j] = bf2add(ac[j], t & ABSM2);            // packed += |diff|
            }
        }
        float s = 0.f;
        #pragma unroll
        for (int j = 0; j < 8; j++) {
            float2 f = __bfloat1622float2(*reinterpret_cast<__nv_bfloat162*>(&ac[j]));
            s += __expf(-f.x) + __expf(-f.y);
        }
        out[(size_t)(rowbase + n) * OUTC + FEAT + lane] = s;
    }
}

extern "C" void kernel_launch(void* const* d_in, const int* in_sizes, int n_in,
                              void* d_out, int out_size) {
    const float* x = (const float*)d_in[0];
    const float* T = (const float*)d_in[1];
    float* out = (float*)d_out;

    convert_T_kernel<<<256, 256>>>(T);

    cudaFuncSetAttribute(fused_kernel, cudaFuncAttributeMaxDynamicSharedMemorySize, SMEM_BYTES);
    fused_kernel<<<NROWS / BM, THREADS, SMEM_BYTES>>>(x, out);
}